// round 1
// baseline (speedup 1.0000x reference)
#include <cuda_runtime.h>
#include <cuda_bf16.h>

// Problem constants (fixed by the dataset shapes)
#define T_TOK 4096   // B*S
#define DD    1024   // model dim
#define EE    8      // experts
#define II    1408   // ffn dim
// top-k = 2 (hardcoded)

// ---------------------------------------------------------------------------
// Static device scratch (allocation inside kernel_launch is forbidden)
// ---------------------------------------------------------------------------
__device__ int   g_count[EE];
__device__ int   g_tok [EE * T_TOK];
__device__ float g_prob[EE * T_TOK];
__device__ int4  g_rec [T_TOK];                       // (e0, slot0, e1, slot1)
__device__ float g_H   [EE * T_TOK * (size_t)II];     // silu(g)*u*prob, per slot
__device__ float g_Yp  [EE * T_TOK * (size_t)DD];     // per-slot expert output

// ---------------------------------------------------------------------------
// 0) reset counters
// ---------------------------------------------------------------------------
__global__ void zero_counts_kernel() {
    if (threadIdx.x < EE) g_count[threadIdx.x] = 0;
}

// ---------------------------------------------------------------------------
// 1) router: scores, top-2, softmax, compaction
//    one block (256 threads = 8 warps) per token; warp w handles expert w
// ---------------------------------------------------------------------------
__global__ __launch_bounds__(256) void router_kernel(
    const float* __restrict__ x, const float* __restrict__ gate_w)
{
    __shared__ float sx[DD];
    __shared__ float sc[EE];
    const int t   = blockIdx.x;
    const int tid = threadIdx.x;

    // load token row into shared (256 * float4 = 1024 floats)
    ((float4*)sx)[tid] = ((const float4*)(x + (size_t)t * DD))[tid];
    __syncthreads();

    const int w = tid >> 5, lane = tid & 31;
    const float* gw = gate_w + w * DD;
    float s = 0.f;
    #pragma unroll 8
    for (int j = lane; j < DD; j += 32) s += sx[j] * gw[j];
    #pragma unroll
    for (int o = 16; o > 0; o >>= 1) s += __shfl_down_sync(0xFFFFFFFFu, s, o);
    if (lane == 0) sc[w] = s;
    __syncthreads();

    if (tid == 0) {
        // top-1 (ties -> lowest index, matching jax.lax.top_k)
        int e0 = 0; float s0 = sc[0];
        #pragma unroll
        for (int e = 1; e < EE; e++) if (sc[e] > s0) { s0 = sc[e]; e0 = e; }
        // top-2
        int e1 = -1; float s1 = -3.0e38f;
        #pragma unroll
        for (int e = 0; e < EE; e++)
            if (e != e0 && sc[e] > s1) { s1 = sc[e]; e1 = e; }
        // softmax over [s0, s1] (s0 >= s1 -> stable)
        float z  = expf(s1 - s0);
        float p1 = z / (1.f + z);
        float p0 = 1.f - p1;

        int sl0 = atomicAdd(&g_count[e0], 1);
        int sl1 = atomicAdd(&g_count[e1], 1);
        g_tok [e0 * T_TOK + sl0] = t;  g_prob[e0 * T_TOK + sl0] = p0;
        g_tok [e1 * T_TOK + sl1] = t;  g_prob[e1 * T_TOK + sl1] = p1;
        g_rec[t] = make_int4(e0, sl0, e1, sl1);
    }
}

// ---------------------------------------------------------------------------
// 2) gemm1: for expert e, rows = routed tokens (gathered), cols = I
//    computes g = Xe @ Wg^T, u = Xe @ Wu^T, writes H = silu(g)*u*prob
//    64x64 tile, K-step 16, 256 threads, 4x4 micro-tile per thread
// ---------------------------------------------------------------------------
__global__ __launch_bounds__(256) void gemm1_kernel(
    const float* __restrict__ x,
    const float* __restrict__ wg,
    const float* __restrict__ wu)
{
    const int e   = blockIdx.z;
    const int cnt = g_count[e];
    const int m0  = blockIdx.y * 64;
    if (m0 >= cnt) return;
    const int n0  = blockIdx.x * 64;

    __shared__ float Xs[16][64];
    __shared__ float Gs[16][64];
    __shared__ float Us[16][64];
    __shared__ int   stok[64];

    const int tid = threadIdx.x;
    if (tid < 64) {
        int m = m0 + tid;
        stok[tid] = g_tok[e * T_TOK + (m < cnt ? m : cnt - 1)];
    }
    __syncthreads();

    const int lm = tid >> 2;          // 0..63 : row within tile being loaded
    const int lk = (tid & 3) << 2;    // 0,4,8,12 : k-offset (float4)
    const int ty = tid >> 4;          // 0..15
    const int tx = tid & 15;          // 0..15

    const float* xrow = x  + (size_t)stok[lm] * DD + lk;
    const float* grow = wg + (size_t)e * II * DD + (size_t)(n0 + lm) * DD + lk;
    const float* urow = wu + (size_t)e * II * DD + (size_t)(n0 + lm) * DD + lk;

    float ag[4][4] = {{0}}, au[4][4] = {{0}};

    for (int k0 = 0; k0 < DD; k0 += 16) {
        float4 xv = *(const float4*)(xrow + k0);
        float4 gv = *(const float4*)(grow + k0);
        float4 uv = *(const float4*)(urow + k0);
        Xs[lk+0][lm]=xv.x; Xs[lk+1][lm]=xv.y; Xs[lk+2][lm]=xv.z; Xs[lk+3][lm]=xv.w;
        Gs[lk+0][lm]=gv.x; Gs[lk+1][lm]=gv.y; Gs[lk+2][lm]=gv.z; Gs[lk+3][lm]=gv.w;
        Us[lk+0][lm]=uv.x; Us[lk+1][lm]=uv.y; Us[lk+2][lm]=uv.z; Us[lk+3][lm]=uv.w;
        __syncthreads();

        #pragma unroll
        for (int kk = 0; kk < 16; kk++) {
            float a0 = Xs[kk][ty], a1 = Xs[kk][ty+16], a2 = Xs[kk][ty+32], a3 = Xs[kk][ty+48];
            float g0 = Gs[kk][tx], g1 = Gs[kk][tx+16], g2 = Gs[kk][tx+32], g3 = Gs[kk][tx+48];
            float u0 = Us[kk][tx], u1 = Us[kk][tx+16], u2 = Us[kk][tx+32], u3 = Us[kk][tx+48];
            ag[0][0]+=a0*g0; ag[0][1]+=a0*g1; ag[0][2]+=a0*g2; ag[0][3]+=a0*g3;
            ag[1][0]+=a1*g0; ag[1][1]+=a1*g1; ag[1][2]+=a1*g2; ag[1][3]+=a1*g3;
            ag[2][0]+=a2*g0; ag[2][1]+=a2*g1; ag[2][2]+=a2*g2; ag[2][3]+=a2*g3;
            ag[3][0]+=a3*g0; ag[3][1]+=a3*g1; ag[3][2]+=a3*g2; ag[3][3]+=a3*g3;
            au[0][0]+=a0*u0; au[0][1]+=a0*u1; au[0][2]+=a0*u2; au[0][3]+=a0*u3;
            au[1][0]+=a1*u0; au[1][1]+=a1*u1; au[1][2]+=a1*u2; au[1][3]+=a1*u3;
            au[2][0]+=a2*u0; au[2][1]+=a2*u1; au[2][2]+=a2*u2; au[2][3]+=a2*u3;
            au[3][0]+=a3*u0; au[3][1]+=a3*u1; au[3][2]+=a3*u2; au[3][3]+=a3*u3;
        }
        __syncthreads();
    }

    #pragma unroll
    for (int i = 0; i < 4; i++) {
        int m = m0 + ty + 16 * i;
        if (m >= cnt) continue;
        float p = g_prob[e * T_TOK + m];
        float* Hrow = g_H + ((size_t)e * T_TOK + m) * II + n0;
        #pragma unroll
        for (int j = 0; j < 4; j++) {
            float gv = ag[i][j];
            float sg = gv / (1.f + __expf(-gv));   // silu
            Hrow[tx + 16 * j] = sg * au[i][j] * p;
        }
    }
}

// ---------------------------------------------------------------------------
// 3) gemm2: per-slot output Yp = H @ Wd^T  (K = I = 1408)
// ---------------------------------------------------------------------------
__global__ __launch_bounds__(256) void gemm2_kernel(const float* __restrict__ wd)
{
    const int e   = blockIdx.z;
    const int cnt = g_count[e];
    const int m0  = blockIdx.y * 64;
    if (m0 >= cnt) return;
    const int n0  = blockIdx.x * 64;

    __shared__ float As[16][64];
    __shared__ float Bs[16][64];

    const int tid = threadIdx.x;
    const int lm = tid >> 2;
    const int lk = (tid & 3) << 2;
    const int ty = tid >> 4;
    const int tx = tid & 15;

    int mrow = m0 + lm; if (mrow >= cnt) mrow = cnt - 1;
    const float* arow = g_H + ((size_t)e * T_TOK + mrow) * II + lk;
    const float* brow = wd  + (size_t)e * DD * II + (size_t)(n0 + lm) * II + lk;

    float acc[4][4] = {{0}};

    for (int k0 = 0; k0 < II; k0 += 16) {
        float4 av = *(const float4*)(arow + k0);
        float4 bv = *(const float4*)(brow + k0);
        As[lk+0][lm]=av.x; As[lk+1][lm]=av.y; As[lk+2][lm]=av.z; As[lk+3][lm]=av.w;
        Bs[lk+0][lm]=bv.x; Bs[lk+1][lm]=bv.y; Bs[lk+2][lm]=bv.z; Bs[lk+3][lm]=bv.w;
        __syncthreads();

        #pragma unroll
        for (int kk = 0; kk < 16; kk++) {
            float a0 = As[kk][ty], a1 = As[kk][ty+16], a2 = As[kk][ty+32], a3 = As[kk][ty+48];
            float b0 = Bs[kk][tx], b1 = Bs[kk][tx+16], b2 = Bs[kk][tx+32], b3 = Bs[kk][tx+48];
            acc[0][0]+=a0*b0; acc[0][1]+=a0*b1; acc[0][2]+=a0*b2; acc[0][3]+=a0*b3;
            acc[1][0]+=a1*b0; acc[1][1]+=a1*b1; acc[1][2]+=a1*b2; acc[1][3]+=a1*b3;
            acc[2][0]+=a2*b0; acc[2][1]+=a2*b1; acc[2][2]+=a2*b2; acc[2][3]+=a2*b3;
            acc[3][0]+=a3*b0; acc[3][1]+=a3*b1; acc[3][2]+=a3*b2; acc[3][3]+=a3*b3;
        }
        __syncthreads();
    }

    #pragma unroll
    for (int i = 0; i < 4; i++) {
        int m = m0 + ty + 16 * i;
        if (m >= cnt) continue;
        float* yrow = g_Yp + ((size_t)e * T_TOK + m) * DD + n0;
        #pragma unroll
        for (int j = 0; j < 4; j++)
            yrow[tx + 16 * j] = acc[i][j];
    }
}

// ---------------------------------------------------------------------------
// 4) combine: out[t] = Yp[e0][s0] + Yp[e1][s1]
// ---------------------------------------------------------------------------
__global__ __launch_bounds__(256) void combine_kernel(float* __restrict__ out)
{
    const int t = blockIdx.x;
    const int4 r = g_rec[t];
    const float4* a = (const float4*)(g_Yp + ((size_t)r.x * T_TOK + r.y) * DD);
    const float4* b = (const float4*)(g_Yp + ((size_t)r.z * T_TOK + r.w) * DD);
    float4* o = (float4*)(out + (size_t)t * DD);
    const int j = threadIdx.x;            // 256 threads * float4 = 1024 floats
    float4 va = a[j], vb = b[j];
    o[j] = make_float4(va.x + vb.x, va.y + vb.y, va.z + vb.z, va.w + vb.w);
}

// ---------------------------------------------------------------------------
// launch
// ---------------------------------------------------------------------------
extern "C" void kernel_launch(void* const* d_in, const int* in_sizes, int n_in,
                              void* d_out, int out_size)
{
    (void)in_sizes; (void)n_in; (void)out_size;
    const float* x  = (const float*)d_in[0];
    const float* gw = (const float*)d_in[1];
    const float* wg = (const float*)d_in[2];
    const float* wu = (const float*)d_in[3];
    const float* wd = (const float*)d_in[4];
    float* out = (float*)d_out;

    zero_counts_kernel<<<1, 32>>>();
    router_kernel<<<T_TOK, 256>>>(x, gw);
    gemm1_kernel<<<dim3(II / 64, T_TOK / 64, EE), 256>>>(x, wg, wu);
    gemm2_kernel<<<dim3(DD / 64, T_TOK / 64, EE), 256>>>(wd);
    combine_kernel<<<T_TOK, 256>>>(out);
}

// round 3
// speedup vs baseline: 3.4500x; 3.4500x over previous
#include <cuda_runtime.h>
#include <cuda_bf16.h>
#include <cstdint>

#define T_TOK 4096   // B*S
#define DD    1024   // model dim
#define EE    8      // experts
#define II    1408   // ffn dim

// ---------------------------------------------------------------------------
// Static device scratch
// ---------------------------------------------------------------------------
__device__ int   g_count[EE];
__device__ int   g_tok [EE * T_TOK];
__device__ float g_prob[EE * T_TOK];
__device__ int4  g_rec [T_TOK];
__device__ __align__(16) __nv_bfloat16 g_Xhi[(size_t)T_TOK * DD];
__device__ __align__(16) __nv_bfloat16 g_Xlo[(size_t)T_TOK * DD];
__device__ __align__(16) __nv_bfloat16 g_Wgh[(size_t)EE * II * DD];
__device__ __align__(16) __nv_bfloat16 g_Wgl[(size_t)EE * II * DD];
__device__ __align__(16) __nv_bfloat16 g_Wuh[(size_t)EE * II * DD];
__device__ __align__(16) __nv_bfloat16 g_Wul[(size_t)EE * II * DD];
__device__ __align__(16) __nv_bfloat16 g_Wdh[(size_t)EE * DD * II];
__device__ __align__(16) __nv_bfloat16 g_Wdl[(size_t)EE * DD * II];
__device__ __align__(16) float         g_G  [(size_t)EE * T_TOK * II];
__device__ __align__(16) float         g_U  [(size_t)EE * T_TOK * II];
__device__ __align__(16) __nv_bfloat16 g_Hhi[(size_t)EE * T_TOK * II];
__device__ __align__(16) __nv_bfloat16 g_Hlo[(size_t)EE * T_TOK * II];
__device__ __align__(16) float         g_Yp [(size_t)EE * T_TOK * DD];

// ---------------------------------------------------------------------------
// PTX helpers (sm_80-era ISA: compiles under plain compute_100 target)
// ---------------------------------------------------------------------------
__device__ __forceinline__ uint32_t smem_u32(const void* p) {
    uint32_t a;
    asm("{ .reg .u64 t; cvta.to.shared.u64 t, %1; cvt.u32.u64 %0, t; }" : "=r"(a) : "l"(p));
    return a;
}

#define CP_ASYNC16(dst, src) \
    asm volatile("cp.async.cg.shared.global [%0], [%1], 16;" :: "r"(dst), "l"(src))
#define CP_COMMIT() asm volatile("cp.async.commit_group;")
#define CP_WAIT0()  asm volatile("cp.async.wait_group 0;")
#define CP_WAIT1()  asm volatile("cp.async.wait_group 1;")

#define LDSM_X4(r0, r1, r2, r3, addr) \
    asm volatile("ldmatrix.sync.aligned.m8n8.x4.shared.b16 {%0,%1,%2,%3}, [%4];" \
        : "=r"(r0), "=r"(r1), "=r"(r2), "=r"(r3) : "r"(addr))

#define MMA16816(d, a, b) \
    asm volatile("mma.sync.aligned.m16n8k16.row.col.f32.bf16.bf16.f32 " \
        "{%0,%1,%2,%3}, {%4,%5,%6,%7}, {%8,%9}, {%0,%1,%2,%3};" \
        : "+f"((d)[0]), "+f"((d)[1]), "+f"((d)[2]), "+f"((d)[3]) \
        : "r"((a)[0]), "r"((a)[1]), "r"((a)[2]), "r"((a)[3]), "r"((b)[0]), "r"((b)[1]))

// smem layout: 80B-padded rows -> conflict-free ldmatrix (stride 80 mod 128
// hits distinct 16B groups for any 8 consecutive rows)
#define ROW_B   80
#define MAT_B   (128 * ROW_B)     // 10240 B per 128x32 bf16 matrix
#define STAGE_B (4 * MAT_B)       // Ahi, Alo, Bhi, Blo
#define SMEM_BYTES (1024 + 2 * STAGE_B)   // 82944

// ---------------------------------------------------------------------------
// 0) reset counters
// ---------------------------------------------------------------------------
__global__ void zero_counts_kernel() {
    if (threadIdx.x < EE) g_count[threadIdx.x] = 0;
}

// ---------------------------------------------------------------------------
// 1) router (unchanged from R1 — verified at 1.15e-6)
// ---------------------------------------------------------------------------
__global__ __launch_bounds__(256) void router_kernel(
    const float* __restrict__ x, const float* __restrict__ gate_w)
{
    __shared__ float sx[DD];
    __shared__ float sc[EE];
    const int t = blockIdx.x, tid = threadIdx.x;
    ((float4*)sx)[tid] = ((const float4*)(x + (size_t)t * DD))[tid];
    __syncthreads();
    const int w = tid >> 5, lane = tid & 31;
    const float* gw = gate_w + w * DD;
    float s = 0.f;
    #pragma unroll 8
    for (int j = lane; j < DD; j += 32) s += sx[j] * gw[j];
    #pragma unroll
    for (int o = 16; o > 0; o >>= 1) s += __shfl_down_sync(0xFFFFFFFFu, s, o);
    if (lane == 0) sc[w] = s;
    __syncthreads();
    if (tid == 0) {
        int e0 = 0; float s0 = sc[0];
        #pragma unroll
        for (int e = 1; e < EE; e++) if (sc[e] > s0) { s0 = sc[e]; e0 = e; }
        int e1 = -1; float s1 = -3.0e38f;
        #pragma unroll
        for (int e = 0; e < EE; e++) if (e != e0 && sc[e] > s1) { s1 = sc[e]; e1 = e; }
        float z = expf(s1 - s0);
        float p1 = z / (1.f + z);
        float p0 = 1.f - p1;
        int sl0 = atomicAdd(&g_count[e0], 1);
        int sl1 = atomicAdd(&g_count[e1], 1);
        g_tok [e0 * T_TOK + sl0] = t;  g_prob[e0 * T_TOK + sl0] = p0;
        g_tok [e1 * T_TOK + sl1] = t;  g_prob[e1 * T_TOK + sl1] = p1;
        g_rec[t] = make_int4(e0, sl0, e1, sl1);
    }
}

// ---------------------------------------------------------------------------
// 2) fp32 -> (bf16 hi, bf16 lo) split
// ---------------------------------------------------------------------------
__global__ __launch_bounds__(256) void split_kernel(const float* __restrict__ s, int which, int n4)
{
    int i = blockIdx.x * 256 + threadIdx.x;
    if (i >= n4) return;
    __nv_bfloat16 *hi, *lo;
    switch (which) {
        case 0:  hi = g_Xhi; lo = g_Xlo; break;
        case 1:  hi = g_Wgh; lo = g_Wgl; break;
        case 2:  hi = g_Wuh; lo = g_Wul; break;
        default: hi = g_Wdh; lo = g_Wdl; break;
    }
    float4 v = ((const float4*)s)[i];
    float vv[4] = {v.x, v.y, v.z, v.w};
    unsigned short h[4], l[4];
    #pragma unroll
    for (int j = 0; j < 4; j++) {
        __nv_bfloat16 a = __float2bfloat16(vv[j]);
        __nv_bfloat16 b = __float2bfloat16(vv[j] - __bfloat162float(a));
        h[j] = __bfloat16_as_ushort(a);
        l[j] = __bfloat16_as_ushort(b);
    }
    *(ushort4*)(hi + 4 * (size_t)i) = make_ushort4(h[0], h[1], h[2], h[3]);
    *(ushort4*)(lo + 4 * (size_t)i) = make_ushort4(l[0], l[1], l[2], l[3]);
}

// ---------------------------------------------------------------------------
// 3) bf16x3 mma.sync GEMM. MODE 0: C = Xe @ {Wg|Wu}^T  (K=1024, N=1408)
//                          MODE 1: Yp = H @ Wd^T       (K=1408, N=1024)
//    128x128x32 block tile, 8 warps (2x4), warp tile 64x32, cp.async 2-stage.
// ---------------------------------------------------------------------------
template<int MODE>
__global__ __launch_bounds__(256) void gemm_mma()
{
    extern __shared__ char smem[];
    const int e     = (MODE == 0) ? (blockIdx.z >> 1) : blockIdx.z;
    const int which = (MODE == 0) ? (blockIdx.z & 1) : 0;
    const int cnt = g_count[e];
    const int m0  = blockIdx.y * 128;
    if (m0 >= cnt) return;
    const int n0  = blockIdx.x * 128;
    const int tid = threadIdx.x;
    const int wid = tid >> 5, lane = tid & 31;
    const int warp_m = wid & 1;   // 0..1  (64 rows each)
    const int warp_n = wid >> 1;  // 0..3  (32 cols each)

    int* s_tok = (int*)smem;
    const uint32_t sd = smem_u32(smem + 1024);

    if (MODE == 0 && tid < 128) {
        int m = m0 + tid;
        s_tok[tid] = g_tok[e * T_TOK + (m < cnt ? m : cnt - 1)];
    }
    __syncthreads();

    constexpr int K  = (MODE == 0) ? DD : II;
    constexpr int NK = K / 32;

    const __nv_bfloat16* Ah_base = (MODE == 0) ? g_Xhi : g_Hhi;
    const __nv_bfloat16* Al_base = (MODE == 0) ? g_Xlo : g_Hlo;
    const __nv_bfloat16* Bh_ptr;
    const __nv_bfloat16* Bl_ptr;
    if (MODE == 0) {
        const size_t wb = (size_t)e * II * DD + (size_t)n0 * DD;
        Bh_ptr = (which ? g_Wuh : g_Wgh) + wb;
        Bl_ptr = (which ? g_Wul : g_Wgl) + wb;
    } else {
        const size_t wb = (size_t)e * DD * II + (size_t)n0 * II;
        Bh_ptr = g_Wdh + wb;
        Bl_ptr = g_Wdl + wb;
    }

    // ---- stage loader -----------------------------------------------------
    auto load_stage = [&](int buf, int kt) {
        const int k0 = kt * 32;
        const uint32_t sbase = sd + buf * STAGE_B;
        #pragma unroll
        for (int i = 0; i < 8; i++) {
            const int idx = tid + 256 * i;
            const int mat = idx >> 9;          // 0:Ahi 1:Alo 2:Bhi 3:Blo
            const int c   = idx & 511;
            const int row = c >> 2;
            const int kc  = c & 3;
            const uint32_t dst = sbase + mat * MAT_B + row * ROW_B + kc * 16;
            const __nv_bfloat16* src;
            if (mat < 2) {
                size_t grow;
                if (MODE == 0) grow = (size_t)s_tok[row];
                else {
                    int r = m0 + row; if (r >= cnt) r = cnt - 1;
                    grow = (size_t)e * T_TOK + r;
                }
                src = (mat == 0 ? Ah_base : Al_base) + grow * (size_t)K + k0 + kc * 8;
            } else {
                src = (mat == 2 ? Bh_ptr : Bl_ptr) + (size_t)row * K + k0 + kc * 8;
            }
            CP_ASYNC16(dst, src);
        }
    };

    float acc[4][4][4] = {};

    load_stage(0, 0);
    CP_COMMIT();
    int buf = 0;

    for (int kt = 0; kt < NK; kt++) {
        if (kt + 1 < NK) {
            load_stage(buf ^ 1, kt + 1);
            CP_COMMIT();
            CP_WAIT1();
        } else {
            CP_WAIT0();
        }
        __syncthreads();

        const uint32_t ah_b = sd + buf * STAGE_B + 0 * MAT_B;
        const uint32_t al_b = sd + buf * STAGE_B + 1 * MAT_B;
        const uint32_t bh_b = sd + buf * STAGE_B + 2 * MAT_B;
        const uint32_t bl_b = sd + buf * STAGE_B + 3 * MAT_B;

        #pragma unroll
        for (int k16 = 0; k16 < 2; k16++) {
            uint32_t ah[4][4], al[4][4], bh[4][2], bl[4][2];
            const uint32_t acol = (k16 * 16 + (lane >> 4) * 8) * 2;
            #pragma unroll
            for (int mf = 0; mf < 4; mf++) {
                const uint32_t ao = (warp_m * 64 + mf * 16 + (lane & 15)) * ROW_B + acol;
                LDSM_X4(ah[mf][0], ah[mf][1], ah[mf][2], ah[mf][3], ah_b + ao);
                LDSM_X4(al[mf][0], al[mf][1], al[mf][2], al[mf][3], al_b + ao);
            }
            const uint32_t bcol = (k16 * 16 + ((lane >> 3) & 1) * 8) * 2;
            #pragma unroll
            for (int nh = 0; nh < 2; nh++) {
                const uint32_t bo = (warp_n * 32 + nh * 16 + (lane >> 4) * 8 + (lane & 7)) * ROW_B + bcol;
                uint32_t r0, r1, r2, r3;
                LDSM_X4(r0, r1, r2, r3, bh_b + bo);
                bh[nh * 2][0] = r0; bh[nh * 2][1] = r1;
                bh[nh * 2 + 1][0] = r2; bh[nh * 2 + 1][1] = r3;
                LDSM_X4(r0, r1, r2, r3, bl_b + bo);
                bl[nh * 2][0] = r0; bl[nh * 2][1] = r1;
                bl[nh * 2 + 1][0] = r2; bl[nh * 2 + 1][1] = r3;
            }
            #pragma unroll
            for (int mf = 0; mf < 4; mf++) {
                #pragma unroll
                for (int nf = 0; nf < 4; nf++) {
                    MMA16816(acc[mf][nf], ah[mf], bh[nf]);
                    MMA16816(acc[mf][nf], ah[mf], bl[nf]);
                    MMA16816(acc[mf][nf], al[mf], bh[nf]);
                }
            }
        }
        __syncthreads();
        buf ^= 1;
    }

    // ---- epilogue ---------------------------------------------------------
    float* Cp;
    size_t ldc;
    if (MODE == 0) {
        Cp  = (which ? g_U : g_G) + (size_t)e * T_TOK * II;
        ldc = II;
    } else {
        Cp  = g_Yp + (size_t)e * T_TOK * DD;
        ldc = DD;
    }
    #pragma unroll
    for (int mf = 0; mf < 4; mf++) {
        const int r0 = m0 + warp_m * 64 + mf * 16 + (lane >> 2);
        #pragma unroll
        for (int nf = 0; nf < 4; nf++) {
            const int col = n0 + warp_n * 32 + nf * 8 + (lane & 3) * 2;
            if (r0 < cnt)
                *(float2*)(Cp + (size_t)r0 * ldc + col) =
                    make_float2(acc[mf][nf][0], acc[mf][nf][1]);
            if (r0 + 8 < cnt)
                *(float2*)(Cp + (size_t)(r0 + 8) * ldc + col) =
                    make_float2(acc[mf][nf][2], acc[mf][nf][3]);
        }
    }
}

// ---------------------------------------------------------------------------
// 4) silu epilogue: H = silu(g)*u*prob -> bf16 hi/lo
// ---------------------------------------------------------------------------
__global__ __launch_bounds__(256) void silu_kernel()
{
    const int e = blockIdx.y, m = blockIdx.x;
    if (m >= g_count[e]) return;
    const float p = g_prob[e * T_TOK + m];
    const size_t base = ((size_t)e * T_TOK + m) * II;
    for (int j4 = threadIdx.x; j4 < II / 4; j4 += 256) {
        float4 g = *(const float4*)(g_G + base + 4 * (size_t)j4);
        float4 u = *(const float4*)(g_U + base + 4 * (size_t)j4);
        float gg[4] = {g.x, g.y, g.z, g.w};
        float uu[4] = {u.x, u.y, u.z, u.w};
        unsigned short hh[4], ll[4];
        #pragma unroll
        for (int j = 0; j < 4; j++) {
            float h = gg[j] / (1.f + __expf(-gg[j])) * uu[j] * p;
            __nv_bfloat16 hi = __float2bfloat16(h);
            __nv_bfloat16 lo = __float2bfloat16(h - __bfloat162float(hi));
            hh[j] = __bfloat16_as_ushort(hi);
            ll[j] = __bfloat16_as_ushort(lo);
        }
        *(ushort4*)(g_Hhi + base + 4 * (size_t)j4) = make_ushort4(hh[0], hh[1], hh[2], hh[3]);
        *(ushort4*)(g_Hlo + base + 4 * (size_t)j4) = make_ushort4(ll[0], ll[1], ll[2], ll[3]);
    }
}

// ---------------------------------------------------------------------------
// 5) combine
// ---------------------------------------------------------------------------
__global__ __launch_bounds__(256) void combine_kernel(float* __restrict__ out)
{
    const int t = blockIdx.x;
    const int4 r = g_rec[t];
    const float4* a = (const float4*)(g_Yp + ((size_t)r.x * T_TOK + r.y) * DD);
    const float4* b = (const float4*)(g_Yp + ((size_t)r.z * T_TOK + r.w) * DD);
    float4* o = (float4*)(out + (size_t)t * DD);
    const int j = threadIdx.x;
    float4 va = a[j], vb = b[j];
    o[j] = make_float4(va.x + vb.x, va.y + vb.y, va.z + vb.z, va.w + vb.w);
}

// ---------------------------------------------------------------------------
// launch
// ---------------------------------------------------------------------------
extern "C" void kernel_launch(void* const* d_in, const int* in_sizes, int n_in,
                              void* d_out, int out_size)
{
    (void)in_sizes; (void)n_in; (void)out_size;
    const float* x  = (const float*)d_in[0];
    const float* gw = (const float*)d_in[1];
    const float* wg = (const float*)d_in[2];
    const float* wu = (const float*)d_in[3];
    const float* wd = (const float*)d_in[4];
    float* out = (float*)d_out;

    cudaFuncSetAttribute(gemm_mma<0>, cudaFuncAttributeMaxDynamicSharedMemorySize, SMEM_BYTES);
    cudaFuncSetAttribute(gemm_mma<1>, cudaFuncAttributeMaxDynamicSharedMemorySize, SMEM_BYTES);

    const int nx4 = T_TOK * DD / 4;
    const int nw4 = EE * II * DD / 4;

    zero_counts_kernel<<<1, 32>>>();
    router_kernel<<<T_TOK, 256>>>(x, gw);
    split_kernel<<<(nx4 + 255) / 256, 256>>>(x,  0, nx4);
    split_kernel<<<(nw4 + 255) / 256, 256>>>(wg, 1, nw4);
    split_kernel<<<(nw4 + 255) / 256, 256>>>(wu, 2, nw4);
    split_kernel<<<(nw4 + 255) / 256, 256>>>(wd, 3, nw4);
    gemm_mma<0><<<dim3(II / 128, T_TOK / 128, EE * 2), 256, SMEM_BYTES>>>();
    silu_kernel<<<dim3(T_TOK, EE), 256>>>();
    gemm_mma<1><<<dim3(DD / 128, T_TOK / 128, EE), 256, SMEM_BYTES>>>();
    combine_kernel<<<T_TOK, 256>>>(out);
}